// round 1
// baseline (speedup 1.0000x reference)
#include <cuda_runtime.h>

#define N_FIRMS 8192
#define DIM 128
#define B_GRID 256   // blocks for the X-pass kernels (4 warps each -> 1024 row-warps)

// Deterministic scratch (allocation-free; __device__ globals are allowed)
__device__ float g_v1[DIM];                    // Wv^T @ head_w
__device__ float g_partial[B_GRID][DIM];       // per-block partials of g = X^T (X v1)
__device__ float g_w[DIM];                     // Wq^T @ (Wk @ g)

// ---------------------------------------------------------------------------
// Kernel A: v1[d] = sum_e Wv[e][d] * head_w[e]      (Wv is row-major [E,D])
// 1 block, 128 threads. Tiny.
// ---------------------------------------------------------------------------
__global__ void kA_v1(const float* __restrict__ Wv,
                      const float* __restrict__ head_w) {
    int d = threadIdx.x;
    float s = 0.0f;
#pragma unroll 8
    for (int e = 0; e < DIM; ++e)
        s += Wv[e * DIM + d] * head_w[e];
    g_v1[d] = s;
}

// ---------------------------------------------------------------------------
// Kernel B: per-block partials of g = X^T (X v1).
// grid = B_GRID blocks x 128 threads (4 warps). One warp handles one row at a
// time (float4 per lane = 128 cols), butterfly-reduces the dot t = X_row . v1,
// then accumulates t * X_row into per-thread registers. Block-level smem
// reduction, then a deterministic store to g_partial[blockIdx].
// ---------------------------------------------------------------------------
__global__ void kB_partial(const float* __restrict__ X) {
    __shared__ float sv1[DIM];
    __shared__ float sacc[4][DIM];

    const int tid  = threadIdx.x;
    const int lane = tid & 31;
    const int wrp  = tid >> 5;

    sv1[tid] = g_v1[tid];
    __syncthreads();

    const float v0 = sv1[lane * 4 + 0];
    const float v1 = sv1[lane * 4 + 1];
    const float v2 = sv1[lane * 4 + 2];
    const float v3 = sv1[lane * 4 + 3];

    float a0 = 0.f, a1 = 0.f, a2 = 0.f, a3 = 0.f;

    for (int row = blockIdx.x * 4 + wrp; row < N_FIRMS; row += B_GRID * 4) {
        const float4 x = *reinterpret_cast<const float4*>(&X[row * DIM + lane * 4]);
        float p = x.x * v0 + x.y * v1 + x.z * v2 + x.w * v3;
#pragma unroll
        for (int o = 16; o > 0; o >>= 1)
            p += __shfl_xor_sync(0xffffffffu, p, o);
        // p == t_row on all lanes
        a0 += p * x.x; a1 += p * x.y; a2 += p * x.z; a3 += p * x.w;
    }

    sacc[wrp][lane * 4 + 0] = a0;
    sacc[wrp][lane * 4 + 1] = a1;
    sacc[wrp][lane * 4 + 2] = a2;
    sacc[wrp][lane * 4 + 3] = a3;
    __syncthreads();

    g_partial[blockIdx.x][tid] =
        sacc[0][tid] + sacc[1][tid] + sacc[2][tid] + sacc[3][tid];
}

// ---------------------------------------------------------------------------
// Kernel C: reduce partials -> g; u = Wk @ g; w = Wq^T @ u.
// 1 block, 128 threads. Deterministic serial reduction over B_GRID partials.
// ---------------------------------------------------------------------------
__global__ void kC_tiny(const float* __restrict__ Wq,
                        const float* __restrict__ Wk) {
    __shared__ float sg[DIM];
    __shared__ float su[DIM];
    const int t = threadIdx.x;

    float g = 0.0f;
#pragma unroll 8
    for (int b = 0; b < B_GRID; ++b)
        g += g_partial[b][t];
    sg[t] = g;
    __syncthreads();

    float u = 0.0f;
#pragma unroll 8
    for (int d = 0; d < DIM; ++d)
        u += Wk[t * DIM + d] * sg[d];
    su[t] = u;
    __syncthreads();

    float w = 0.0f;
#pragma unroll 8
    for (int e = 0; e < DIM; ++e)
        w += Wq[e * DIM + t] * su[e];
    g_w[t] = w;
}

// ---------------------------------------------------------------------------
// Kernel D: preds[i] = X[i] . w + b. Warp per row, butterfly reduce.
// ---------------------------------------------------------------------------
__global__ void kD_out(const float* __restrict__ X,
                       const float* __restrict__ head_b,
                       float* __restrict__ out) {
    __shared__ float sw[DIM];
    const int tid  = threadIdx.x;
    const int lane = tid & 31;
    const int wrp  = tid >> 5;

    sw[tid] = g_w[tid];
    __syncthreads();

    const float w0 = sw[lane * 4 + 0];
    const float w1 = sw[lane * 4 + 1];
    const float w2 = sw[lane * 4 + 2];
    const float w3 = sw[lane * 4 + 3];
    const float b  = head_b[0];

    for (int row = blockIdx.x * 4 + wrp; row < N_FIRMS; row += B_GRID * 4) {
        const float4 x = *reinterpret_cast<const float4*>(&X[row * DIM + lane * 4]);
        float p = x.x * w0 + x.y * w1 + x.z * w2 + x.w * w3;
#pragma unroll
        for (int o = 16; o > 0; o >>= 1)
            p += __shfl_xor_sync(0xffffffffu, p, o);
        if (lane == 0)
            out[row] = p + b;
    }
}

// ---------------------------------------------------------------------------
// Launch: X, Wq, Wk, Wv, head_w, head_b  ->  preds (float, 8192)
// ---------------------------------------------------------------------------
extern "C" void kernel_launch(void* const* d_in, const int* in_sizes, int n_in,
                              void* d_out, int out_size) {
    const float* X      = (const float*)d_in[0];
    const float* Wq     = (const float*)d_in[1];
    const float* Wk     = (const float*)d_in[2];
    const float* Wv     = (const float*)d_in[3];
    const float* head_w = (const float*)d_in[4];
    const float* head_b = (const float*)d_in[5];
    float* out          = (float*)d_out;

    kA_v1<<<1, DIM>>>(Wv, head_w);
    kB_partial<<<B_GRID, DIM>>>(X);
    kC_tiny<<<1, DIM>>>(Wq, Wk);
    kD_out<<<B_GRID, DIM>>>(X, head_b, out);
}

// round 2
// speedup vs baseline: 1.5985x; 1.5985x over previous
#include <cuda_runtime.h>

#define DIM      128
#define NROWS    8192
#define GRID     128          // <= 148 SMs -> all CTAs co-resident, barrier is safe
#define BLOCK    512
#define NWARPS   16           // warps per block; 128 blocks * 16 warps * 4 rows = 8192

// Allocation-free scratch + barrier state (__device__ globals are allowed)
__device__ float        g_partial[GRID][DIM];
__device__ unsigned int g_count = 0;   // resets to 0 at every barrier
__device__ unsigned int g_gen   = 0;   // monotone across graph replays

__global__ void __launch_bounds__(BLOCK, 1)
fused_linattn(const float* __restrict__ X,
              const float* __restrict__ Wq,
              const float* __restrict__ Wk,
              const float* __restrict__ Wv,
              const float* __restrict__ head_w,
              const float* __restrict__ head_b,
              float* __restrict__ out) {
    __shared__ float svw[DIM];            // v1 in phase 0/1, w in phase 3
    __shared__ float sacc[NWARPS][DIM];   // per-warp g partials
    __shared__ float sred[4][DIM];        // quarter-sums of cross-block reduce
    __shared__ float sg[DIM];             // g
    __shared__ float su[DIM];             // u = Wk @ g

    const int tid  = threadIdx.x;
    const int lane = tid & 31;
    const int wrp  = tid >> 5;
    const int bid  = blockIdx.x;

    // ---------------- Phase 0: v1 = Wv^T @ head_w (threads 0..127) ----------
    if (tid < DIM) {
        float s = 0.0f;
#pragma unroll 16
        for (int e = 0; e < DIM; ++e)
            s += Wv[e * DIM + tid] * head_w[e];
        svw[tid] = s;
    }
    __syncthreads();

    const float v0 = svw[lane * 4 + 0];
    const float v1 = svw[lane * 4 + 1];
    const float v2 = svw[lane * 4 + 2];
    const float v3 = svw[lane * 4 + 3];

    // ---------------- Phase 1: partial g = X^T (X v1), 4 rows per warp ------
    // Exact mapping: warp (bid*16 + wrp) owns rows 4w .. 4w+3.
    const int  row0 = (bid * NWARPS + wrp) * 4;
    const int  coff = lane * 4;

    // 4 independent loads in flight (MLP=4). These registers stay live through
    // the barrier so the final X @ w pass needs NO memory reads.
    const float4 x0 = *reinterpret_cast<const float4*>(&X[(row0 + 0) * DIM + coff]);
    const float4 x1 = *reinterpret_cast<const float4*>(&X[(row0 + 1) * DIM + coff]);
    const float4 x2 = *reinterpret_cast<const float4*>(&X[(row0 + 2) * DIM + coff]);
    const float4 x3 = *reinterpret_cast<const float4*>(&X[(row0 + 3) * DIM + coff]);

    float p0 = x0.x * v0 + x0.y * v1 + x0.z * v2 + x0.w * v3;
    float p1 = x1.x * v0 + x1.y * v1 + x1.z * v2 + x1.w * v3;
    float p2 = x2.x * v0 + x2.y * v1 + x2.z * v2 + x2.w * v3;
    float p3 = x3.x * v0 + x3.y * v1 + x3.z * v2 + x3.w * v3;
#pragma unroll
    for (int o = 16; o > 0; o >>= 1) {   // 4 independent butterfly chains
        p0 += __shfl_xor_sync(0xffffffffu, p0, o);
        p1 += __shfl_xor_sync(0xffffffffu, p1, o);
        p2 += __shfl_xor_sync(0xffffffffu, p2, o);
        p3 += __shfl_xor_sync(0xffffffffu, p3, o);
    }
    // accumulate t_row * X_row per column slice
    sacc[wrp][coff + 0] = p0 * x0.x + p1 * x1.x + p2 * x2.x + p3 * x3.x;
    sacc[wrp][coff + 1] = p0 * x0.y + p1 * x1.y + p2 * x2.y + p3 * x3.y;
    sacc[wrp][coff + 2] = p0 * x0.z + p1 * x1.z + p2 * x2.z + p3 * x3.z;
    sacc[wrp][coff + 3] = p0 * x0.w + p1 * x1.w + p2 * x2.w + p3 * x3.w;
    __syncthreads();

    if (tid < DIM) {
        float s = 0.0f;
#pragma unroll
        for (int w = 0; w < NWARPS; ++w)
            s += sacc[w][tid];
        g_partial[bid][tid] = s;
    }
    __syncthreads();

    // ---------------- Grid barrier (sense-free, monotone generation) --------
    if (tid == 0) {
        __threadfence();                                   // publish g_partial
        const unsigned my_gen = *(volatile unsigned*)&g_gen;
        if (atomicAdd(&g_count, 1u) == GRID - 1) {
            g_count = 0;
            __threadfence();
            atomicAdd(&g_gen, 1u);                         // release
        } else {
            while (*(volatile unsigned*)&g_gen == my_gen) { }
        }
        __threadfence();                                   // acquire
    }
    __syncthreads();

    // ---------------- Phase 2: g -> u = Wk g -> w = Wq^T u (per block) ------
    {   // parallel cross-block reduce: 4 quarters of 32 partials each
        const int t = tid & 127;
        const int q = tid >> 7;          // 0..3
        float s = 0.0f;
#pragma unroll
        for (int b = q * 32; b < q * 32 + 32; ++b)
            s += g_partial[b][t];
        sred[q][t] = s;
    }
    __syncthreads();
    if (tid < DIM)
        sg[tid] = sred[0][tid] + sred[1][tid] + sred[2][tid] + sred[3][tid];
    __syncthreads();
    if (tid < DIM) {
        float u = 0.0f;
#pragma unroll 16
        for (int d = 0; d < DIM; ++d)
            u += Wk[tid * DIM + d] * sg[d];
        su[tid] = u;
    }
    __syncthreads();
    if (tid < DIM) {
        float w = 0.0f;
#pragma unroll 16
        for (int e = 0; e < DIM; ++e)
            w += Wq[e * DIM + tid] * su[e];
        svw[tid] = w;
    }
    __syncthreads();

    // ---------------- Phase 3: out = X @ w + b (X still in registers) -------
    const float w0 = svw[lane * 4 + 0];
    const float w1 = svw[lane * 4 + 1];
    const float w2 = svw[lane * 4 + 2];
    const float w3 = svw[lane * 4 + 3];

    float q0 = x0.x * w0 + x0.y * w1 + x0.z * w2 + x0.w * w3;
    float q1 = x1.x * w0 + x1.y * w1 + x1.z * w2 + x1.w * w3;
    float q2 = x2.x * w0 + x2.y * w1 + x2.z * w2 + x2.w * w3;
    float q3 = x3.x * w0 + x3.y * w1 + x3.z * w2 + x3.w * w3;
#pragma unroll
    for (int o = 16; o > 0; o >>= 1) {
        q0 += __shfl_xor_sync(0xffffffffu, q0, o);
        q1 += __shfl_xor_sync(0xffffffffu, q1, o);
        q2 += __shfl_xor_sync(0xffffffffu, q2, o);
        q3 += __shfl_xor_sync(0xffffffffu, q3, o);
    }
    if (lane == 0) {
        const float b = head_b[0];
        float4 r = make_float4(q0 + b, q1 + b, q2 + b, q3 + b);
        *reinterpret_cast<float4*>(&out[row0]) = r;   // rows are consecutive
    }
}

extern "C" void kernel_launch(void* const* d_in, const int* in_sizes, int n_in,
                              void* d_out, int out_size) {
    const float* X      = (const float*)d_in[0];
    const float* Wq     = (const float*)d_in[1];
    const float* Wk     = (const float*)d_in[2];
    const float* Wv     = (const float*)d_in[3];
    const float* head_w = (const float*)d_in[4];
    const float* head_b = (const float*)d_in[5];
    float* out          = (float*)d_out;

    fused_linattn<<<GRID, BLOCK>>>(X, Wq, Wk, Wv, head_w, head_b, out);
}

// round 3
// speedup vs baseline: 3.1254x; 1.9552x over previous
#include <cuda_runtime.h>

#define DIM      128
#define GRID     128          // <= 148 SMs -> all CTAs co-resident, barrier is safe
#define BLOCK    512
#define NWARPS   16           // 128 blocks * 16 warps * 4 rows = 8192 rows

// Allocation-free scratch + barrier state
__device__ float        g_partial[GRID][DIM];
__device__ unsigned int g_count = 0;   // resets to 0 at every barrier
__device__ unsigned int g_gen   = 0;   // monotone across graph replays

__global__ void __launch_bounds__(BLOCK, 1)
fused_linattn(const float* __restrict__ X,
              const float* __restrict__ Wq,
              const float* __restrict__ Wk,
              const float* __restrict__ Wv,
              const float* __restrict__ head_w,
              const float* __restrict__ head_b,
              float* __restrict__ out) {
    __shared__ float svw[DIM];            // v1 (phases 0-1), then w (phase 3)
    __shared__ float sacc[NWARPS][DIM];   // per-warp partial rows
    __shared__ float sred[4][DIM];        // quarter sums
    __shared__ float sg[DIM];             // g
    __shared__ float su[DIM];             // u = Wk @ g

    const int tid  = threadIdx.x;
    const int lane = tid & 31;
    const int wrp  = tid >> 5;
    const int bid  = blockIdx.x;
    const int coff = lane * 4;
    const int dq   = tid & 127;           // (d, quarter) split for reductions
    const int qq   = tid >> 7;

    // ============ Phase 0: v1 = Wv^T @ head_w, warp-parallel depth-8 ========
    {
        const int e0 = wrp * 8;
        float ax = 0.f, ay = 0.f, az = 0.f, aw = 0.f;
#pragma unroll
        for (int j = 0; j < 8; ++j) {
            const float  hw = head_w[e0 + j];
            const float4 wv = *reinterpret_cast<const float4*>(&Wv[(e0 + j) * DIM + coff]);
            ax += hw * wv.x; ay += hw * wv.y; az += hw * wv.z; aw += hw * wv.w;
        }
        sacc[wrp][coff + 0] = ax; sacc[wrp][coff + 1] = ay;
        sacc[wrp][coff + 2] = az; sacc[wrp][coff + 3] = aw;
    }
    __syncthreads();
    sred[qq][dq] = sacc[qq * 4 + 0][dq] + sacc[qq * 4 + 1][dq]
                 + sacc[qq * 4 + 2][dq] + sacc[qq * 4 + 3][dq];
    __syncthreads();
    if (tid < DIM)
        svw[tid] = sred[0][tid] + sred[1][tid] + sred[2][tid] + sred[3][tid];
    __syncthreads();

    const float v0 = svw[coff + 0];
    const float v1 = svw[coff + 1];
    const float v2 = svw[coff + 2];
    const float v3 = svw[coff + 3];

    // ============ Phase 1: partial g = X^T (X v1), 4 rows per warp ==========
    const int row0 = (bid * NWARPS + wrp) * 4;

    const float4 x0 = *reinterpret_cast<const float4*>(&X[(row0 + 0) * DIM + coff]);
    const float4 x1 = *reinterpret_cast<const float4*>(&X[(row0 + 1) * DIM + coff]);
    const float4 x2 = *reinterpret_cast<const float4*>(&X[(row0 + 2) * DIM + coff]);
    const float4 x3 = *reinterpret_cast<const float4*>(&X[(row0 + 3) * DIM + coff]);

    float p0 = x0.x * v0 + x0.y * v1 + x0.z * v2 + x0.w * v3;
    float p1 = x1.x * v0 + x1.y * v1 + x1.z * v2 + x1.w * v3;
    float p2 = x2.x * v0 + x2.y * v1 + x2.z * v2 + x2.w * v3;
    float p3 = x3.x * v0 + x3.y * v1 + x3.z * v2 + x3.w * v3;
#pragma unroll
    for (int o = 16; o > 0; o >>= 1) {
        p0 += __shfl_xor_sync(0xffffffffu, p0, o);
        p1 += __shfl_xor_sync(0xffffffffu, p1, o);
        p2 += __shfl_xor_sync(0xffffffffu, p2, o);
        p3 += __shfl_xor_sync(0xffffffffu, p3, o);
    }
    __syncthreads();   // sacc reuse guard (cheap, all warps hit it together)
    sacc[wrp][coff + 0] = p0 * x0.x + p1 * x1.x + p2 * x2.x + p3 * x3.x;
    sacc[wrp][coff + 1] = p0 * x0.y + p1 * x1.y + p2 * x2.y + p3 * x3.y;
    sacc[wrp][coff + 2] = p0 * x0.z + p1 * x1.z + p2 * x2.z + p3 * x3.z;
    sacc[wrp][coff + 3] = p0 * x0.w + p1 * x1.w + p2 * x2.w + p3 * x3.w;
    __syncthreads();
    sred[qq][dq] = sacc[qq * 4 + 0][dq] + sacc[qq * 4 + 1][dq]
                 + sacc[qq * 4 + 2][dq] + sacc[qq * 4 + 3][dq];
    __syncthreads();
    if (tid < DIM)
        g_partial[bid][tid] = sred[0][tid] + sred[1][tid] + sred[2][tid] + sred[3][tid];
    __syncthreads();

    // ============ Grid barrier (monotone generation; graph-replay safe) =====
    if (tid == 0) {
        __threadfence();
        const unsigned my_gen = *(volatile unsigned*)&g_gen;
        if (atomicAdd(&g_count, 1u) == GRID - 1) {
            g_count = 0;
            __threadfence();
            atomicAdd(&g_gen, 1u);
        } else {
            while (*(volatile unsigned*)&g_gen == my_gen) { }
        }
        __threadfence();
    }
    __syncthreads();

    // ============ Phase 2a: g = sum of partials (quarter-split over blocks) ==
    {
        float s = 0.0f;
#pragma unroll
        for (int b = qq * 32; b < qq * 32 + 32; ++b)
            s += g_partial[b][dq];
        sred[qq][dq] = s;
    }
    __syncthreads();
    if (tid < DIM)
        sg[tid] = sred[0][tid] + sred[1][tid] + sred[2][tid] + sred[3][tid];
    __syncthreads();

    // ============ Phase 2b: u = Wk @ g, warp-parallel, 8 rows per warp ======
    {
        const float s0 = sg[coff + 0], s1 = sg[coff + 1];
        const float s2 = sg[coff + 2], s3 = sg[coff + 3];
        const int r0 = wrp * 8;
        float pu[8];
#pragma unroll
        for (int j = 0; j < 8; ++j) {
            const float4 kk = *reinterpret_cast<const float4*>(&Wk[(r0 + j) * DIM + coff]);
            pu[j] = kk.x * s0 + kk.y * s1 + kk.z * s2 + kk.w * s3;
        }
#pragma unroll
        for (int o = 16; o > 0; o >>= 1) {
#pragma unroll
            for (int j = 0; j < 8; ++j)
                pu[j] += __shfl_xor_sync(0xffffffffu, pu[j], o);
        }
        if (lane == 0) {
            su[r0 + 0] = pu[0]; su[r0 + 1] = pu[1];
            su[r0 + 2] = pu[2]; su[r0 + 3] = pu[3];
            su[r0 + 4] = pu[4]; su[r0 + 5] = pu[5];
            su[r0 + 6] = pu[6]; su[r0 + 7] = pu[7];
        }
    }
    __syncthreads();

    // ============ Phase 2c: w = Wq^T @ u, warp-parallel depth-8 =============
    {
        const int e0 = wrp * 8;
        float ax = 0.f, ay = 0.f, az = 0.f, aw = 0.f;
#pragma unroll
        for (int j = 0; j < 8; ++j) {
            const float  uu = su[e0 + j];
            const float4 wq = *reinterpret_cast<const float4*>(&Wq[(e0 + j) * DIM + coff]);
            ax += uu * wq.x; ay += uu * wq.y; az += uu * wq.z; aw += uu * wq.w;
        }
        sacc[wrp][coff + 0] = ax; sacc[wrp][coff + 1] = ay;
        sacc[wrp][coff + 2] = az; sacc[wrp][coff + 3] = aw;
    }
    __syncthreads();
    sred[qq][dq] = sacc[qq * 4 + 0][dq] + sacc[qq * 4 + 1][dq]
                 + sacc[qq * 4 + 2][dq] + sacc[qq * 4 + 3][dq];
    __syncthreads();
    if (tid < DIM)
        svw[tid] = sred[0][tid] + sred[1][tid] + sred[2][tid] + sred[3][tid];
    __syncthreads();

    // ============ Phase 3: out = X @ w + b (X still in registers) ===========
    const float w0 = svw[coff + 0];
    const float w1 = svw[coff + 1];
    const float w2 = svw[coff + 2];
    const float w3 = svw[coff + 3];

    float q0 = x0.x * w0 + x0.y * w1 + x0.z * w2 + x0.w * w3;
    float q1 = x1.x * w0 + x1.y * w1 + x1.z * w2 + x1.w * w3;
    float q2 = x2.x * w0 + x2.y * w1 + x2.z * w2 + x2.w * w3;
    float q3 = x3.x * w0 + x3.y * w1 + x3.z * w2 + x3.w * w3;
#pragma unroll
    for (int o = 16; o > 0; o >>= 1) {
        q0 += __shfl_xor_sync(0xffffffffu, q0, o);
        q1 += __shfl_xor_sync(0xffffffffu, q1, o);
        q2 += __shfl_xor_sync(0xffffffffu, q2, o);
        q3 += __shfl_xor_sync(0xffffffffu, q3, o);
    }
    if (lane == 0) {
        const float b = head_b[0];
        *reinterpret_cast<float4*>(&out[row0]) =
            make_float4(q0 + b, q1 + b, q2 + b, q3 + b);
    }
}

extern "C" void kernel_launch(void* const* d_in, const int* in_sizes, int n_in,
                              void* d_out, int out_size) {
    const float* X      = (const float*)d_in[0];
    const float* Wq     = (const float*)d_in[1];
    const float* Wk     = (const float*)d_in[2];
    const float* Wv     = (const float*)d_in[3];
    const float* head_w = (const float*)d_in[4];
    const float* head_b = (const float*)d_in[5];
    float* out          = (float*)d_out;

    fused_linattn<<<GRID, BLOCK>>>(X, Wq, Wk, Wv, head_w, head_b, out);
}